// round 12
// baseline (speedup 1.0000x reference)
#include <cuda_runtime.h>
#include <math.h>

#define MAXF 200000

// Per-fragment accumulator: 16 floats, 64B-aligned.
//  0: sum fx   1: sum fy   2: sum fz   3: count
//  4: sum px   5: sum py   6: sum pz   7: sum (p x f).x
//  8: (pxf).y  9: (pxf).z 10: sum pxx 11: sum pyy
// 12: sum pzz 13: sum pxy 14: sum pxz 15: sum pyz
// Zero-initialized at module load; frag_kernel restores zeros after each
// consume, so every graph replay sees a zeroed accumulator (self-cleaning).
__device__ __align__(16) float g_acc[16 * MAXF];

__device__ __forceinline__ void red_v4(float* addr, float a, float b, float c, float d) {
    asm volatile("red.global.add.v4.f32 [%0], {%1,%2,%3,%4};"
                 :: "l"(addr), "f"(a), "f"(b), "f"(c), "f"(d) : "memory");
}

__global__ void scatter_kernel(const float* __restrict__ f_atom,
                               const float* __restrict__ atom_pos,
                               const int*   __restrict__ frag_id,
                               int N) {
    int i = blockIdx.x * blockDim.x + threadIdx.x;
    if (i >= N) return;

    // Streaming loads (evict-first): inputs are read exactly once per replay;
    // keep them from evicting the L2-resident accumulator that REDG targets.
    int fid = __ldcs(&frag_id[i]);

    float fx = __ldcs(&f_atom[3 * i + 0]);
    float fy = __ldcs(&f_atom[3 * i + 1]);
    float fz = __ldcs(&f_atom[3 * i + 2]);
    float px = __ldcs(&atom_pos[3 * i + 0]);
    float py = __ldcs(&atom_pos[3 * i + 1]);
    float pz = __ldcs(&atom_pos[3 * i + 2]);

    // p x f
    float cx = py * fz - pz * fy;
    float cy = pz * fx - px * fz;
    float cz = px * fy - py * fx;

    float* base = g_acc + (size_t)fid * 16;
    red_v4(base +  0, fx, fy, fz, 1.0f);
    red_v4(base +  4, px, py, pz, cx);
    red_v4(base +  8, cy, cz, px * px, py * py);
    red_v4(base + 12, pz * pz, px * py, px * pz, py * pz);
}

// Eigenvector of symmetric 3x3 (a00,a11,a22,a01,a02,a12) for eigenvalue lam:
// null-space of M = A - lam*I via the largest of the three row-pair cross
// products (rows of M span the complement of the eigenvector). Sign arbitrary.
__device__ __forceinline__ void eigvec3(
        float a00, float a11, float a22, float a01, float a02, float a12,
        float lam, float* vx, float* vy, float* vz) {
    float m00 = a00 - lam, m11 = a11 - lam, m22 = a22 - lam;
    // r0 = (m00, a01, a02); r1 = (a01, m11, a12); r2 = (a02, a12, m22)
    float c0x = a01 * a12 - a02 * m11;   // r0 x r1
    float c0y = a02 * a01 - m00 * a12;
    float c0z = m00 * m11 - a01 * a01;
    float c1x = a01 * m22 - a02 * a12;   // r0 x r2
    float c1y = a02 * a02 - m00 * m22;
    float c1z = m00 * a12 - a01 * a02;
    float c2x = m11 * m22 - a12 * a12;   // r1 x r2
    float c2y = a12 * a02 - a01 * m22;
    float c2z = a01 * a12 - m11 * a02;

    float n0 = c0x * c0x + c0y * c0y + c0z * c0z;
    float n1 = c1x * c1x + c1y * c1y + c1z * c1z;
    float n2 = c2x * c2x + c2y * c2y + c2z * c2z;

    bool b01 = n0 >= n1;
    float mxx = b01 ? c0x : c1x;
    float mxy = b01 ? c0y : c1y;
    float mxz = b01 ? c0z : c1z;
    float nm  = b01 ? n0 : n1;
    bool b2 = nm >= n2;
    float sx = b2 ? mxx : c2x;
    float sy = b2 ? mxy : c2y;
    float sz = b2 ? mxz : c2z;
    float nf = b2 ? nm : n2;

    float inv = rsqrtf(nf + 1e-35f);
    *vx = sx * inv; *vy = sy * inv; *vz = sz * inv;
}

__global__ void __launch_bounds__(128) frag_kernel(
        const float* __restrict__ T_frag,
        const int*   __restrict__ frag_sizes,
        float* __restrict__ out, int F) {
    int f = blockIdx.x * blockDim.x + threadIdx.x;
    if (f >= F) return;

    float4* acc4 = reinterpret_cast<float4*>(g_acc) + (size_t)f * 4;
    float4 a0 = acc4[0];
    float4 a1 = acc4[1];
    float4 a2 = acc4[2];
    float4 a3 = acc4[3];

    // Self-clean for the next graph replay (stream order guarantees the
    // next scatter starts after this kernel finishes).
    float4 z = make_float4(0.f, 0.f, 0.f, 0.f);
    acc4[0] = z; acc4[1] = z; acc4[2] = z; acc4[3] = z;

    float sfx = a0.x, sfy = a0.y, sfz = a0.z, n = a0.w;
    float spx = a1.x, spy = a1.y, spz = a1.z;
    float crx = a1.w, cry = a2.x, crz = a2.y;
    float sxx = a2.z, syy = a2.w, szz = a3.x;
    float sxy = a3.y, sxz = a3.z, syz = a3.w;

    float Tx = T_frag[3 * f + 0];
    float Ty = T_frag[3 * f + 1];
    float Tz = T_frag[3 * f + 2];

    float dinv = __fdividef(1.0f, fmaxf(n, 1.0f));
    float vfx = sfx * dinv, vfy = sfy * dinv, vfz = sfz * dinv;

    // torque = sum(p x f) - T x (sum f)
    float tx = crx - (Ty * sfz - Tz * sfy);
    float ty = cry - (Tz * sfx - Tx * sfz);
    float tz = crz - (Tx * sfy - Ty * sfx);

    // Centered second moments
    float Sxx = sxx - 2.f * Tx * spx + n * Tx * Tx;
    float Syy = syy - 2.f * Ty * spy + n * Ty * Ty;
    float Szz = szz - 2.f * Tz * spz + n * Tz * Tz;
    float Sxy = sxy - Tx * spy - Ty * spx + n * Tx * Ty;
    float Sxz = sxz - Tx * spz - Tz * spx + n * Tx * Tz;
    float Syz = syz - Ty * spz - Tz * spy + n * Ty * Tz;

    // I = tr(S) * eye - S  (symmetric: diag a00,a11,a22; off a01,a02,a12)
    float a00 = Syy + Szz, a11 = Sxx + Szz, a22 = Sxx + Syy;
    float a01 = -Sxy, a02 = -Sxz, a12 = -Syz;

    // ---- Closed-form eigenvalues (symmetric 3x3, trigonometric method) ----
    float q = (a00 + a11 + a22) * (1.0f / 3.0f);
    float b00 = a00 - q, b11 = a11 - q, b22 = a22 - q;
    float p1 = a01 * a01 + a02 * a02 + a12 * a12;
    float p2 = b00 * b00 + b11 * b11 + b22 * b22 + 2.0f * p1;
    float pp = sqrtf(p2 * (1.0f / 6.0f));
    float pinv = __fdividef(1.0f, fmaxf(pp, 1e-20f));
    float c00 = b00 * pinv, c11 = b11 * pinv, c22 = b22 * pinv;
    float c01 = a01 * pinv, c02 = a02 * pinv, c12 = a12 * pinv;
    float detB = c00 * (c11 * c22 - c12 * c12)
               - c01 * (c01 * c22 - c12 * c02)
               + c02 * (c01 * c12 - c11 * c02);
    float r = 0.5f * detB;
    r = fminf(fmaxf(r, -1.0f), 1.0f);
    float phi = acosf(r) * (1.0f / 3.0f);
    // w0 >= w1 >= w2
    float w0 = q + 2.0f * pp * cosf(phi);
    float w2 = q + 2.0f * pp * cosf(phi + 2.0943951023931953f); // + 2*pi/3
    float w1 = 3.0f * q - w0 - w2;
    float w[3] = {w0, w1, w2};

    // ---- Eigenvectors: independent null-space extraction (high ILP) ----
    float V[3][3];  // V[row][i] = component row of eigenvector i (columns)
    eigvec3(a00, a11, a22, a01, a02, a12, w0, &V[0][0], &V[1][0], &V[2][0]);
    eigvec3(a00, a11, a22, a01, a02, a12, w1, &V[0][1], &V[1][1], &V[2][1]);
    eigvec3(a00, a11, a22, a01, a02, a12, w2, &V[0][2], &V[1][2], &V[2][2]);

    float maxe = fmaxf(w0, 1e-8f);

    int fs = frag_sizes[f];
    float gate = (fs <= 1) ? 0.0f : 1.0f;
    float obs[3];
    #pragma unroll
    for (int i = 0; i < 3; i++)
        obs[i] = (w[i] > 0.01f * maxe) ? gate : 0.0f;

    float coef[3];
    #pragma unroll
    for (int i = 0; i < 3; i++) {
        float te = V[0][i] * tx + V[1][i] * ty + V[2][i] * tz;
        coef[i] = __fdividef(te, fmaxf(w[i], 1e-6f)) * obs[i];
    }

    float om[3];
    #pragma unroll
    for (int j = 0; j < 3; j++)
        om[j] = V[j][0] * coef[0] + V[j][1] * coef[1] + V[j][2] * coef[2];

    out[3 * f + 0] = vfx;
    out[3 * f + 1] = vfy;
    out[3 * f + 2] = vfz;

    float* o_om = out + 3 * F;
    o_om[3 * f + 0] = om[0];
    o_om[3 * f + 1] = om[1];
    o_om[3 * f + 2] = om[2];

    float* o_P = out + 6 * F;
    #pragma unroll
    for (int j = 0; j < 3; j++)
        #pragma unroll
        for (int k2 = 0; k2 < 3; k2++) {
            float pv = V[j][0] * obs[0] * V[k2][0]
                     + V[j][1] * obs[1] * V[k2][1]
                     + V[j][2] * obs[2] * V[k2][2];
            o_P[9 * f + 3 * j + k2] = pv;
        }
}

extern "C" void kernel_launch(void* const* d_in, const int* in_sizes, int n_in,
                              void* d_out, int out_size) {
    const float* f_atom     = (const float*)d_in[0];
    const float* atom_pos   = (const float*)d_in[1];
    const float* T_frag     = (const float*)d_in[2];
    const int*   frag_id    = (const int*)d_in[3];
    const int*   frag_sizes = (const int*)d_in[4];

    int N = in_sizes[0] / 3;
    int F = in_sizes[2] / 3;

    float* out = (float*)d_out;

    scatter_kernel<<<(N + 255) / 256, 256>>>(f_atom, atom_pos, frag_id, N);
    frag_kernel<<<(F + 127) / 128, 128>>>(T_frag, frag_sizes, out, F);
}

// round 13
// speedup vs baseline: 1.0189x; 1.0189x over previous
#include <cuda_runtime.h>
#include <math.h>

#define MAXF 200000

// Per-fragment accumulator: 16 floats, 64B-aligned.
//  0: sum fx   1: sum fy   2: sum fz   3: count
//  4: sum px   5: sum py   6: sum pz   7: sum (p x f).x
//  8: (pxf).y  9: (pxf).z 10: sum pxx 11: sum pyy
// 12: sum pzz 13: sum pxy 14: sum pxz 15: sum pyz
// Zero-initialized at module load; frag_kernel restores zeros after each
// consume, so every graph replay sees a zeroed accumulator (self-cleaning).
__device__ __align__(16) float g_acc[16 * MAXF];

__device__ __forceinline__ void red_v4(float* addr, float a, float b, float c, float d) {
    asm volatile("red.global.add.v4.f32 [%0], {%1,%2,%3,%4};"
                 :: "l"(addr), "f"(a), "f"(b), "f"(c), "f"(d) : "memory");
}

__global__ void scatter_kernel(const float* __restrict__ f_atom,
                               const float* __restrict__ atom_pos,
                               const int*   __restrict__ frag_id,
                               int N) {
    int i = blockIdx.x * blockDim.x + threadIdx.x;
    if (i >= N) return;

    // Streaming loads (evict-first): inputs are read exactly once per replay;
    // keep them from evicting the L2-resident accumulator that REDG targets.
    int fid = __ldcs(&frag_id[i]);

    float fx = __ldcs(&f_atom[3 * i + 0]);
    float fy = __ldcs(&f_atom[3 * i + 1]);
    float fz = __ldcs(&f_atom[3 * i + 2]);
    float px = __ldcs(&atom_pos[3 * i + 0]);
    float py = __ldcs(&atom_pos[3 * i + 1]);
    float pz = __ldcs(&atom_pos[3 * i + 2]);

    // p x f
    float cx = py * fz - pz * fy;
    float cy = pz * fx - px * fz;
    float cz = px * fy - py * fx;

    float* base = g_acc + (size_t)fid * 16;
    red_v4(base +  0, fx, fy, fz, 1.0f);
    red_v4(base +  4, px, py, pz, cx);
    red_v4(base +  8, cy, cz, px * px, py * py);
    red_v4(base + 12, pz * pz, px * py, px * pz, py * pz);
}

// Eigenvalue-only branchless Jacobi (3 sweeps, proven minimum): no V
// tracking, just diagonalizes A. Half-angle form, 2 rsqrt per rotation.
__device__ __forceinline__ void jacobi3_eigvals(float A[3][3]) {
    #pragma unroll 1
    for (int sweep = 0; sweep < 3; sweep++) {
        #pragma unroll
        for (int k = 0; k < 3; k++) {
            const int p = (k == 2) ? 1 : 0;
            const int q = (k == 0) ? 1 : 2;
            const int r = 3 - p - q;

            float apq = A[p][q];
            float u = A[q][q] - A[p][p];
            u = u + copysignf(1e-35f, u);        // u=v=0 -> identity rot
            float v = 2.0f * apq;

            float rinv = rsqrtf(u * u + v * v);  // MUFU 1
            float cos2 = fabsf(u) * rinv;
            float c2 = 0.5f * (1.0f + cos2);     // cos^2(phi) >= 0.5
            float cinv = rsqrtf(c2);             // MUFU 2
            float c = c2 * cinv;
            float s = 0.5f * v * copysignf(rinv, u) * cinv;

            float s2 = s * s;
            float sc2 = 2.0f * s * c;

            float app = A[p][p];
            float aqq = A[q][q];
            float napp = c2 * app + s2 * aqq - sc2 * apq;
            float naqq = s2 * app + c2 * aqq + sc2 * apq;

            float arp = A[r][p];
            float arq = A[r][q];
            float nrp = c * arp - s * arq;
            float nrq = s * arp + c * arq;

            A[p][p] = napp;
            A[q][q] = naqq;
            A[p][q] = 0.f; A[q][p] = 0.f;
            A[r][p] = nrp; A[p][r] = nrp;
            A[r][q] = nrq; A[q][r] = nrq;
        }
    }
}

// Eigenvector of symmetric 3x3 for eigenvalue lam: null-space of A - lam*I
// via the largest of the three row-pair cross products. Sign arbitrary
// (outputs are quadratic/bilinear in V). Validated in R12 at 7.3e-5 rel_err.
__device__ __forceinline__ void eigvec3(
        float a00, float a11, float a22, float a01, float a02, float a12,
        float lam, float* vx, float* vy, float* vz) {
    float m00 = a00 - lam, m11 = a11 - lam, m22 = a22 - lam;
    float c0x = a01 * a12 - a02 * m11;   // r0 x r1
    float c0y = a02 * a01 - m00 * a12;
    float c0z = m00 * m11 - a01 * a01;
    float c1x = a01 * m22 - a02 * a12;   // r0 x r2
    float c1y = a02 * a02 - m00 * m22;
    float c1z = m00 * a12 - a01 * a02;
    float c2x = m11 * m22 - a12 * a12;   // r1 x r2
    float c2y = a12 * a02 - a01 * m22;
    float c2z = a01 * a12 - m11 * a02;

    float n0 = c0x * c0x + c0y * c0y + c0z * c0z;
    float n1 = c1x * c1x + c1y * c1y + c1z * c1z;
    float n2 = c2x * c2x + c2y * c2y + c2z * c2z;

    bool b01 = n0 >= n1;
    float mxx = b01 ? c0x : c1x;
    float mxy = b01 ? c0y : c1y;
    float mxz = b01 ? c0z : c1z;
    float nm  = b01 ? n0 : n1;
    bool b2 = nm >= n2;
    float sx = b2 ? mxx : c2x;
    float sy = b2 ? mxy : c2y;
    float sz = b2 ? mxz : c2z;
    float nf = b2 ? nm : n2;

    float inv = rsqrtf(nf + 1e-35f);
    *vx = sx * inv; *vy = sy * inv; *vz = sz * inv;
}

__global__ void __launch_bounds__(128) frag_kernel(
        const float* __restrict__ T_frag,
        const int*   __restrict__ frag_sizes,
        float* __restrict__ out, int F) {
    int f = blockIdx.x * blockDim.x + threadIdx.x;
    if (f >= F) return;

    float4* acc4 = reinterpret_cast<float4*>(g_acc) + (size_t)f * 4;
    float4 a0 = acc4[0];
    float4 a1 = acc4[1];
    float4 a2 = acc4[2];
    float4 a3 = acc4[3];

    // Self-clean for the next graph replay (stream order guarantees the
    // next scatter starts after this kernel finishes).
    float4 z = make_float4(0.f, 0.f, 0.f, 0.f);
    acc4[0] = z; acc4[1] = z; acc4[2] = z; acc4[3] = z;

    float sfx = a0.x, sfy = a0.y, sfz = a0.z, n = a0.w;
    float spx = a1.x, spy = a1.y, spz = a1.z;
    float crx = a1.w, cry = a2.x, crz = a2.y;
    float sxx = a2.z, syy = a2.w, szz = a3.x;
    float sxy = a3.y, sxz = a3.z, syz = a3.w;

    float Tx = T_frag[3 * f + 0];
    float Ty = T_frag[3 * f + 1];
    float Tz = T_frag[3 * f + 2];

    float dinv = __fdividef(1.0f, fmaxf(n, 1.0f));
    float vfx = sfx * dinv, vfy = sfy * dinv, vfz = sfz * dinv;

    // torque = sum(p x f) - T x (sum f)
    float tx = crx - (Ty * sfz - Tz * sfy);
    float ty = cry - (Tz * sfx - Tx * sfz);
    float tz = crz - (Tx * sfy - Ty * sfx);

    // Centered second moments
    float Sxx = sxx - 2.f * Tx * spx + n * Tx * Tx;
    float Syy = syy - 2.f * Ty * spy + n * Ty * Ty;
    float Szz = szz - 2.f * Tz * spz + n * Tz * Tz;
    float Sxy = sxy - Tx * spy - Ty * spx + n * Tx * Ty;
    float Sxz = sxz - Tx * spz - Tz * spx + n * Tx * Tz;
    float Syz = syz - Ty * spz - Tz * spy + n * Ty * Tz;

    // I = tr(S) * eye - S  (symmetric)
    float a00 = Syy + Szz, a11 = Sxx + Szz, a22 = Sxx + Syy;
    float a01 = -Sxy, a02 = -Sxz, a12 = -Syz;

    // Eigenvalues via 3-sweep Jacobi (no V tracking)
    float A[3][3];
    A[0][0] = a00; A[1][1] = a11; A[2][2] = a22;
    A[0][1] = a01; A[1][0] = a01;
    A[0][2] = a02; A[2][0] = a02;
    A[1][2] = a12; A[2][1] = a12;
    jacobi3_eigvals(A);
    float w[3] = {A[0][0], A[1][1], A[2][2]};

    // Eigenvectors: independent null-space extraction (high ILP)
    float V[3][3];  // columns = eigenvectors
    eigvec3(a00, a11, a22, a01, a02, a12, w[0], &V[0][0], &V[1][0], &V[2][0]);
    eigvec3(a00, a11, a22, a01, a02, a12, w[1], &V[0][1], &V[1][1], &V[2][1]);
    eigvec3(a00, a11, a22, a01, a02, a12, w[2], &V[0][2], &V[1][2], &V[2][2]);

    float maxe = fmaxf(fmaxf(w[0], w[1]), w[2]);
    maxe = fmaxf(maxe, 1e-8f);

    int fs = frag_sizes[f];
    float gate = (fs <= 1) ? 0.0f : 1.0f;
    float obs[3];
    #pragma unroll
    for (int i = 0; i < 3; i++)
        obs[i] = (w[i] > 0.01f * maxe) ? gate : 0.0f;

    float coef[3];
    #pragma unroll
    for (int i = 0; i < 3; i++) {
        float te = V[0][i] * tx + V[1][i] * ty + V[2][i] * tz;
        coef[i] = __fdividef(te, fmaxf(w[i], 1e-6f)) * obs[i];
    }

    float om[3];
    #pragma unroll
    for (int j = 0; j < 3; j++)
        om[j] = V[j][0] * coef[0] + V[j][1] * coef[1] + V[j][2] * coef[2];

    out[3 * f + 0] = vfx;
    out[3 * f + 1] = vfy;
    out[3 * f + 2] = vfz;

    float* o_om = out + 3 * F;
    o_om[3 * f + 0] = om[0];
    o_om[3 * f + 1] = om[1];
    o_om[3 * f + 2] = om[2];

    float* o_P = out + 6 * F;
    #pragma unroll
    for (int j = 0; j < 3; j++)
        #pragma unroll
        for (int k2 = 0; k2 < 3; k2++) {
            float pv = V[j][0] * obs[0] * V[k2][0]
                     + V[j][1] * obs[1] * V[k2][1]
                     + V[j][2] * obs[2] * V[k2][2];
            o_P[9 * f + 3 * j + k2] = pv;
        }
}

extern "C" void kernel_launch(void* const* d_in, const int* in_sizes, int n_in,
                              void* d_out, int out_size) {
    const float* f_atom     = (const float*)d_in[0];
    const float* atom_pos   = (const float*)d_in[1];
    const float* T_frag     = (const float*)d_in[2];
    const int*   frag_id    = (const int*)d_in[3];
    const int*   frag_sizes = (const int*)d_in[4];

    int N = in_sizes[0] / 3;
    int F = in_sizes[2] / 3;

    float* out = (float*)d_out;

    scatter_kernel<<<(N + 255) / 256, 256>>>(f_atom, atom_pos, frag_id, N);
    frag_kernel<<<(F + 127) / 128, 128>>>(T_frag, frag_sizes, out, F);
}

// round 15
// speedup vs baseline: 1.0265x; 1.0075x over previous
#include <cuda_runtime.h>
#include <math.h>

#define MAXF 200000

// Per-fragment accumulator: 16 floats, 64B-aligned.
//  0: sum fx   1: sum fy   2: sum fz   3: count
//  4: sum px   5: sum py   6: sum pz   7: sum (p x f).x
//  8: (pxf).y  9: (pxf).z 10: sum pxx 11: sum pyy
// 12: sum pzz 13: sum pxy 14: sum pxz 15: sum pyz
// Zero-initialized at module load; frag_kernel restores zeros after each
// consume, so every graph replay sees a zeroed accumulator (self-cleaning).
// 16 f32 scalars = 4 x red.v4 messages/atom: the PTX minimum (red .f32 is
// capped at .v4/128-bit) and the information minimum for this decomposition.
__device__ __align__(64) float g_acc[16 * MAXF];

__device__ __forceinline__ void red_v4(float* addr, float a, float b, float c, float d) {
    asm volatile("red.global.add.v4.f32 [%0], {%1,%2,%3,%4};"
                 :: "l"(addr), "f"(a), "f"(b), "f"(c), "f"(d) : "memory");
}

__global__ void scatter_kernel(const float* __restrict__ f_atom,
                               const float* __restrict__ atom_pos,
                               const int*   __restrict__ frag_id,
                               int N) {
    int i = blockIdx.x * blockDim.x + threadIdx.x;
    if (i >= N) return;

    // Streaming loads (evict-first): inputs are read exactly once per replay;
    // keep them from evicting the L2-resident accumulator that REDG targets.
    int fid = __ldcs(&frag_id[i]);

    float fx = __ldcs(&f_atom[3 * i + 0]);
    float fy = __ldcs(&f_atom[3 * i + 1]);
    float fz = __ldcs(&f_atom[3 * i + 2]);
    float px = __ldcs(&atom_pos[3 * i + 0]);
    float py = __ldcs(&atom_pos[3 * i + 1]);
    float pz = __ldcs(&atom_pos[3 * i + 2]);

    float* base = g_acc + (size_t)fid * 16;

    // First message depends only on raw loads — issue before computing
    // products so the REDG stream starts while FMA fills the rest.
    red_v4(base + 0, fx, fy, fz, 1.0f);

    // p x f
    float cx = py * fz - pz * fy;
    float cy = pz * fx - px * fz;
    float cz = px * fy - py * fx;

    red_v4(base +  4, px, py, pz, cx);
    red_v4(base +  8, cy, cz, px * px, py * py);
    red_v4(base + 12, pz * pz, px * py, px * pz, py * pz);
}

// Branchless Jacobi for symmetric 3x3: 3 fixed sweeps (9 rotations) — the
// measured minimum (2 sweeps breaks omega at 1.8e-3 rel_err; 3 gives 5e-7).
// Sweep loop kept rolled (schedules better than full unroll, R7 vs R8).
// 2 rsqrt per rotation (half-angle form, no divisions).
// A destroyed to diagonal; V holds eigenvectors as COLUMNS (A = V D V^T).
// Degenerate u=v=0 guarded by bias -> identity rotation.
__device__ __forceinline__ void jacobi3(float A[3][3], float V[3][3]) {
    V[0][0] = 1.f; V[0][1] = 0.f; V[0][2] = 0.f;
    V[1][0] = 0.f; V[1][1] = 1.f; V[1][2] = 0.f;
    V[2][0] = 0.f; V[2][1] = 0.f; V[2][2] = 1.f;

    #pragma unroll 1
    for (int sweep = 0; sweep < 3; sweep++) {
        #pragma unroll
        for (int k = 0; k < 3; k++) {
            const int p = (k == 2) ? 1 : 0;
            const int q = (k == 0) ? 1 : 2;
            const int r = 3 - p - q;

            float apq = A[p][q];
            float u = A[q][q] - A[p][p];
            u = u + copysignf(1e-35f, u);        // u=v=0 -> identity rot
            float v = 2.0f * apq;

            float rinv = rsqrtf(u * u + v * v);  // MUFU 1
            float cos2 = fabsf(u) * rinv;        // in [0,1]
            float c2 = 0.5f * (1.0f + cos2);     // cos^2(phi) >= 0.5
            float cinv = rsqrtf(c2);             // MUFU 2
            float c = c2 * cinv;                 // cos(phi)
            float s = 0.5f * v * copysignf(rinv, u) * cinv;  // sin(phi)

            float s2 = s * s;
            float sc2 = 2.0f * s * c;

            float app = A[p][p];
            float aqq = A[q][q];
            float napp = c2 * app + s2 * aqq - sc2 * apq;
            float naqq = s2 * app + c2 * aqq + sc2 * apq;

            float arp = A[r][p];
            float arq = A[r][q];
            float nrp = c * arp - s * arq;
            float nrq = s * arp + c * arq;

            A[p][p] = napp;
            A[q][q] = naqq;
            A[p][q] = 0.f; A[q][p] = 0.f;
            A[r][p] = nrp; A[p][r] = nrp;
            A[r][q] = nrq; A[q][r] = nrq;

            #pragma unroll
            for (int i = 0; i < 3; i++) {
                float vip = V[i][p];
                float viq = V[i][q];
                V[i][p] = c * vip - s * viq;
                V[i][q] = s * vip + c * viq;
            }
        }
    }
}

__global__ void __launch_bounds__(128) frag_kernel(
        const float* __restrict__ T_frag,
        const int*   __restrict__ frag_sizes,
        float* __restrict__ out, int F) {
    int f = blockIdx.x * blockDim.x + threadIdx.x;
    if (f >= F) return;

    float4* acc4 = reinterpret_cast<float4*>(g_acc) + (size_t)f * 4;
    float4 a0 = acc4[0];
    float4 a1 = acc4[1];
    float4 a2 = acc4[2];
    float4 a3 = acc4[3];

    // Self-clean for the next graph replay (stream order guarantees the
    // next scatter starts after this kernel finishes).
    float4 z = make_float4(0.f, 0.f, 0.f, 0.f);
    acc4[0] = z; acc4[1] = z; acc4[2] = z; acc4[3] = z;

    float sfx = a0.x, sfy = a0.y, sfz = a0.z, n = a0.w;
    float spx = a1.x, spy = a1.y, spz = a1.z;
    float crx = a1.w, cry = a2.x, crz = a2.y;
    float sxx = a2.z, syy = a2.w, szz = a3.x;
    float sxy = a3.y, sxz = a3.z, syz = a3.w;

    float Tx = T_frag[3 * f + 0];
    float Ty = T_frag[3 * f + 1];
    float Tz = T_frag[3 * f + 2];

    float dinv = __fdividef(1.0f, fmaxf(n, 1.0f));
    float vx = sfx * dinv, vy = sfy * dinv, vz = sfz * dinv;

    // torque = sum(p x f) - T x (sum f)
    float tx = crx - (Ty * sfz - Tz * sfy);
    float ty = cry - (Tz * sfx - Tx * sfz);
    float tz = crz - (Tx * sfy - Ty * sfx);

    // Centered second moments
    float Sxx = sxx - 2.f * Tx * spx + n * Tx * Tx;
    float Syy = syy - 2.f * Ty * spy + n * Ty * Ty;
    float Szz = szz - 2.f * Tz * spz + n * Tz * Tz;
    float Sxy = sxy - Tx * spy - Ty * spx + n * Tx * Ty;
    float Sxz = sxz - Tx * spz - Tz * spx + n * Tx * Tz;
    float Syz = syz - Ty * spz - Tz * spy + n * Ty * Tz;

    // I = tr(S) * eye - S
    float A[3][3];
    A[0][0] = Syy + Szz;  A[1][1] = Sxx + Szz;  A[2][2] = Sxx + Syy;
    A[0][1] = -Sxy; A[1][0] = -Sxy;
    A[0][2] = -Sxz; A[2][0] = -Sxz;
    A[1][2] = -Syz; A[2][1] = -Syz;

    float V[3][3];
    jacobi3(A, V);
    float w[3] = {A[0][0], A[1][1], A[2][2]};

    float maxe = fmaxf(fmaxf(w[0], w[1]), w[2]);
    maxe = fmaxf(maxe, 1e-8f);

    int fs = frag_sizes[f];
    float gate = (fs <= 1) ? 0.0f : 1.0f;
    float obs[3];
    #pragma unroll
    for (int i = 0; i < 3; i++)
        obs[i] = (w[i] > 0.01f * maxe) ? gate : 0.0f;

    float coef[3];
    #pragma unroll
    for (int i = 0; i < 3; i++) {
        float te = V[0][i] * tx + V[1][i] * ty + V[2][i] * tz;
        coef[i] = __fdividef(te, fmaxf(w[i], 1e-6f)) * obs[i];
    }

    float om[3];
    #pragma unroll
    for (int j = 0; j < 3; j++)
        om[j] = V[j][0] * coef[0] + V[j][1] * coef[1] + V[j][2] * coef[2];

    out[3 * f + 0] = vx;
    out[3 * f + 1] = vy;
    out[3 * f + 2] = vz;

    float* o_om = out + 3 * F;
    o_om[3 * f + 0] = om[0];
    o_om[3 * f + 1] = om[1];
    o_om[3 * f + 2] = om[2];

    float* o_P = out + 6 * F;
    #pragma unroll
    for (int j = 0; j < 3; j++)
        #pragma unroll
        for (int k2 = 0; k2 < 3; k2++) {
            float pv = V[j][0] * obs[0] * V[k2][0]
                     + V[j][1] * obs[1] * V[k2][1]
                     + V[j][2] * obs[2] * V[k2][2];
            o_P[9 * f + 3 * j + k2] = pv;
        }
}

extern "C" void kernel_launch(void* const* d_in, const int* in_sizes, int n_in,
                              void* d_out, int out_size) {
    const float* f_atom     = (const float*)d_in[0];
    const float* atom_pos   = (const float*)d_in[1];
    const float* T_frag     = (const float*)d_in[2];
    const int*   frag_id    = (const int*)d_in[3];
    const int*   frag_sizes = (const int*)d_in[4];

    int N = in_sizes[0] / 3;
    int F = in_sizes[2] / 3;

    float* out = (float*)d_out;

    scatter_kernel<<<(N + 255) / 256, 256>>>(f_atom, atom_pos, frag_id, N);
    frag_kernel<<<(F + 127) / 128, 128>>>(T_frag, frag_sizes, out, F);
}